// round 12
// baseline (speedup 1.0000x reference)
#include <cuda_runtime.h>
#include <cuda_fp16.h>
#include <cstdint>

#define NN 50000
#define EE 800000
#define KF 256
#define HH 8
#define WROWS 768   // [Wq;Wk;Wv]

// ---------------------------------------------------------------------------
// Scratch (static device globals; no allocation anywhere)
// ---------------------------------------------------------------------------
__device__ __align__(16) __half g_q[(size_t)NN * 256];
__device__ __align__(16) __half g_k[(size_t)NN * 256];
__device__ __align__(16) float g_sum[NN * HH];
__device__ __align__(16) __half g_wh[(size_t)WROWS * KF];

// ---------------------------------------------------------------------------
__device__ __forceinline__ uint32_t smem_u32(const void* p) {
    uint32_t a;
    asm("{ .reg .u64 t; cvta.to.shared.u64 t, %1; cvt.u32.u64 %0, t; }" : "=r"(a) : "l"(p));
    return a;
}
__device__ __forceinline__ void ldsm_x4(uint32_t* r, uint32_t addr) {
    asm volatile("ldmatrix.sync.aligned.m8n8.x4.shared.b16 {%0,%1,%2,%3}, [%4];"
                 : "=r"(r[0]), "=r"(r[1]), "=r"(r[2]), "=r"(r[3]) : "r"(addr));
}
__device__ __forceinline__ void mma_f16(float* c, const uint32_t* a, uint32_t b0, uint32_t b1) {
    asm volatile(
        "mma.sync.aligned.m16n8k16.row.col.f32.f16.f16.f32 "
        "{%0,%1,%2,%3}, {%4,%5,%6,%7}, {%8,%9}, {%0,%1,%2,%3};"
        : "+f"(c[0]), "+f"(c[1]), "+f"(c[2]), "+f"(c[3])
        : "r"(a[0]), "r"(a[1]), "r"(a[2]), "r"(a[3]), "r"(b0), "r"(b1));
}
__device__ __forceinline__ void cp_async16(uint32_t smem_addr, const void* gptr) {
    asm volatile("cp.async.cg.shared.global [%0], [%1], 16;"
                 :: "r"(smem_addr), "l"(gptr) : "memory");
}
#define CP_COMMIT() asm volatile("cp.async.commit_group;" ::: "memory")
#define CP_WAIT(n)  asm volatile("cp.async.wait_group %0;" :: "n"(n) : "memory")

// ---------------------------------------------------------------------------
// Prep: W concat -> g_wh (fp16); zero g_sum.
// ---------------------------------------------------------------------------
#define WGROUPS (WROWS * KF / 4)       // 49,152
#define ZGROUPS (NN * HH / 4)          // 100,000
__global__ void __launch_bounds__(256) prep_kernel(
    const float* __restrict__ Wq, const float* __restrict__ Wk, const float* __restrict__ Wv)
{
    int idx = blockIdx.x * 256 + threadIdx.x;
    if (idx >= WGROUPS) {
        int z = idx - WGROUPS;
        if (z < ZGROUPS)
            *(float4*)(g_sum + (size_t)z * 4) = make_float4(0.f, 0.f, 0.f, 0.f);
        return;
    }
    size_t off = (size_t)idx * 4;
    size_t row = off / KF;
    const float* Wm = (row < 256) ? Wq : (row < 512) ? Wk : Wv;
    const float* src = Wm - ((row < 256) ? 0 : (row < 512) ? 256 * KF : 512 * KF);
    float4 v = *(const float4*)(src + off);
    __half2 p0 = __floats2half2_rn(v.x, v.y);
    __half2 p1 = __floats2half2_rn(v.z, v.w);
    uint2 u;
    u.x = *(uint32_t*)&p0; u.y = *(uint32_t*)&p1;
    *(uint2*)(g_wh + off) = u;
}

// ---------------------------------------------------------------------------
// Fused A-resident QKV GEMM (fp16 mma.sync): C[N,768] = x @ W^T + b
// Each CTA: BM=64 rows of x, converted fp32->fp16 once into SMEM, then
// nNt column tiles of BN=128 (nt: 0-1 q | 2-3 k | 4-5 v-transposed).
// B streams via 4-stage cp.async ring (W is L2-resident).
// 8 warps, warp tile 32x32; acc = 32 floats/thread.
// ---------------------------------------------------------------------------
#define AROW 264u                     // halves per A row (256+8 pad)
#define ABYTES (64u * AROW * 2u)      // 33792
#define BROW 80u                      // bytes per B row (40 halves)
#define BSTAGE (128u * BROW)          // 10240
#define NSTAGE 4
#define OFF_B ABYTES                  // 33792
#define BRING (NSTAGE * BSTAGE)       // 40960
#define OFF_VSTG (OFF_B + BRING)      // 74752
#define SMEM_QK OFF_VSTG              // 74752 (qk launch: no vstage)
#define VSTG_BYTES (64u * 132u * 4u)  // 33792
#define SMEM_V (OFF_VSTG + VSTG_BYTES) // 108544

extern __shared__ char dynsmem[];

__global__ void __launch_bounds__(256, 2) gemm_fused(
    int ntBegin, int nNt,
    const float* __restrict__ x,
    const float* __restrict__ bq, const float* __restrict__ bk, const float* __restrict__ bv,
    float* __restrict__ out_v)
{
    const int t = threadIdx.x;
    const int wid = t >> 5;
    const int lane = t & 31;
    const int mT = blockIdx.x;          // 0..781

    const int wm = (wid >> 2) * 32;     // 0 or 32
    const int wn = (wid & 3) * 32;      // 0,32,64,96

    const uint32_t sb = smem_u32(dynsmem);

    // ---- B loader mapping (slice = 128 rows x 32 halves) ----
    const int lrow = t >> 1;            // 0..127
    const int lhalf = t & 1;
    const uint32_t dstB0 = sb + OFF_B + (uint32_t)lrow * BROW + (uint32_t)lhalf * 32u;
    const int S = nNt * 8;

    auto issueB = [&](int s) {
        if (s < S) {
            const int nt = ntBegin + (s >> 3), ks = s & 7;
            const uint32_t st = (uint32_t)(s & 3) * BSTAGE;
            const __half* bp = g_wh + (size_t)(nt * 128 + lrow) * KF + ks * 32 + lhalf * 16;
            cp_async16(dstB0 + st, bp);
            cp_async16(dstB0 + st + 16u, bp + 8);
        }
        CP_COMMIT();
    };

    issueB(0); issueB(1); issueB(2);

    // ---- A prologue: load 64 rows of x (fp32), convert to fp16 SMEM ----
    {
        const int row = t >> 2;          // 0..63
        const int qtr = t & 3;           // quarter of the 256-col row
        const int grow = mT * 64 + row;
        const bool ok = (grow < NN);
        const float* xp = x + (size_t)grow * KF + qtr * 64;
        char* arow = dynsmem + (size_t)row * (AROW * 2) + (size_t)qtr * 128;  // 64 halves = 128B
#pragma unroll
        for (int j = 0; j < 16; j++) {
            float4 v = ok ? *(const float4*)(xp + j * 4) : make_float4(0.f, 0.f, 0.f, 0.f);
            __half2 p0 = __floats2half2_rn(v.x, v.y);
            __half2 p1 = __floats2half2_rn(v.z, v.w);
            uint2 u;
            u.x = *(uint32_t*)&p0; u.y = *(uint32_t*)&p1;
            *(uint2*)(arow + j * 8) = u;
        }
    }
    __syncthreads();

    // ---- ldmatrix addresses ----
    const int rA = (lane & 15);
    const int cA = (lane >> 4) << 3;
    const int rB = (lane & 7) + ((lane >> 4) << 3);
    const int cB = ((lane >> 3) & 1) << 3;

    uint32_t addrA[2], addrB[2];
#pragma unroll
    for (int mi = 0; mi < 2; mi++)
        addrA[mi] = sb + (uint32_t)(wm + mi * 16 + rA) * (AROW * 2u) + (uint32_t)cA * 2u;
#pragma unroll
    for (int nf2 = 0; nf2 < 2; nf2++)
        addrB[nf2] = sb + OFF_B + (uint32_t)(wn + nf2 * 16 + rB) * BROW + (uint32_t)cB * 2u;

    const int g = lane >> 2, tg = lane & 3;

    for (int ntl = 0; ntl < nNt; ntl++) {
        const int nt = ntBegin + ntl;

        float acc[2][4][4];
#pragma unroll
        for (int mi = 0; mi < 2; mi++)
#pragma unroll
            for (int nf = 0; nf < 4; nf++)
#pragma unroll
                for (int i = 0; i < 4; i++) acc[mi][nf][i] = 0.f;

#pragma unroll
        for (int ks = 0; ks < 8; ks++) {
            const int s = ntl * 8 + ks;
            CP_WAIT(2);
            __syncthreads();
            issueB(s + 3);

            const uint32_t stB = (uint32_t)(s & 3) * BSTAGE;
            const uint32_t aOff = (uint32_t)ks * 64u;   // ks*32 halves
#pragma unroll
            for (int kk = 0; kk < 2; kk++) {
                uint32_t afrag[2][4];
                ldsm_x4(afrag[0], addrA[0] + aOff + kk * 32);
                ldsm_x4(afrag[1], addrA[1] + aOff + kk * 32);
                uint32_t bfrag[2][4];
                ldsm_x4(bfrag[0], addrB[0] + stB + kk * 32);
                ldsm_x4(bfrag[1], addrB[1] + stB + kk * 32);
#pragma unroll
                for (int mi = 0; mi < 2; mi++)
#pragma unroll
                    for (int nf = 0; nf < 4; nf++)
                        mma_f16(acc[mi][nf], afrag[mi],
                                bfrag[nf >> 1][(nf & 1) * 2],
                                bfrag[nf >> 1][(nf & 1) * 2 + 1]);
            }
        }

        // ---- epilogue for this nt ----
        if (nt < 4) {
            // q/k: direct half2 stores
            const bool isQ = (nt < 2);
            const float* bptr = isQ ? bq : bk;
            __half* dst = isQ ? g_q : g_k;
            const int colBase = (nt & 1) * 128;
#pragma unroll
            for (int mi = 0; mi < 2; mi++) {
#pragma unroll
                for (int hh = 0; hh < 2; hh++) {
                    const int gr = mT * 64 + wm + mi * 16 + g + hh * 8;
                    if (gr >= NN) continue;
#pragma unroll
                    for (int nf = 0; nf < 4; nf++) {
                        const int lc = colBase + wn + nf * 8 + tg * 2;
                        float v0 = acc[mi][nf][hh * 2]     + __ldg(bptr + lc);
                        float v1 = acc[mi][nf][hh * 2 + 1] + __ldg(bptr + lc + 1);
                        __half2 p2 = __floats2half2_rn(v0, v1);
                        *(__half2*)(dst + (size_t)gr * 256 + lc) = p2;
                    }
                }
            }
        } else {
            // v: stage 64x128 into dedicated SMEM (compact 4d+h), coalesced out
            float* stg = (float*)(dynsmem + OFF_VSTG);
            const int wcBase = (nt - 4) * 128;
#pragma unroll
            for (int mi = 0; mi < 2; mi++) {
#pragma unroll
                for (int hh = 0; hh < 2; hh++) {
                    const int lr = wm + mi * 16 + g + hh * 8;   // 0..63
#pragma unroll
                    for (int nf = 0; nf < 4; nf++) {
                        const int c0 = wn + nf * 8 + tg * 2;    // 0..127
                        float v0 = acc[mi][nf][hh * 2]     + __ldg(bv + wcBase + c0);
                        float v1 = acc[mi][nf][hh * 2 + 1] + __ldg(bv + wcBase + c0 + 1);
                        stg[lr * 132 + 4 * (c0 & 31) + (c0 >> 5)] = v0;
                        stg[lr * 132 + 4 * ((c0 + 1) & 31) + ((c0 + 1) >> 5)] = v1;
                    }
                }
            }
            __syncthreads();
#pragma unroll
            for (int it = 0; it < 8; it++) {
                const int idx = it * 256 + t;      // 0..2047
                const int r = idx >> 5, d = idx & 31;
                const int gr = mT * 64 + r;
                if (gr < NN) {
                    float4 v4 = *(float4*)&stg[r * 132 + 4 * d];
                    *(float4*)(out_v + (size_t)gr * 256 + d * 8 + (nt - 4) * 4) = v4;
                }
            }
            __syncthreads();   // protect stg before next nt reuses it
        }
    }
}

// ---------------------------------------------------------------------------
// Pass 1: 4 edges/warp, 8 lanes/edge, contiguous 16B chunks per lane.
// ---------------------------------------------------------------------------
__global__ void __launch_bounds__(256) edge_pass1(
    const int* __restrict__ edge,
    const float* __restrict__ ew,
    float* __restrict__ out_att)
{
    const int lane = threadIdx.x & 31;
    const int wid = threadIdx.x >> 5;
    const int e = blockIdx.x * 32 + wid * 4 + (lane >> 3);
    const int l = lane & 7;

    const int src = __ldg(edge + e);
    const int dst = __ldg(edge + EE + e);
    const float w = __ldg(ew + e);

    const uint4* qb = (const uint4*)(g_q + (size_t)src * 256);
    const uint4* kb = (const uint4*)(g_k + (size_t)dst * 256);

    uint4 qv[4], kv[4];
#pragma unroll
    for (int i = 0; i < 4; i++) { qv[i] = qb[i * 8 + l]; kv[i] = kb[i * 8 + l]; }

    float pp[4];
#pragma unroll
    for (int i = 0; i < 4; i++) {
        const __half2* qh = (const __half2*)&qv[i];
        const __half2* kh = (const __half2*)&kv[i];
        __half2 hacc = __hmul2(qh[0], kh[0]);
        hacc = __hfma2(qh[1], kh[1], hacc);
        hacc = __hfma2(qh[2], kh[2], hacc);
        hacc = __hfma2(qh[3], kh[3], hacc);
        float2 f2 = __half22float2(hacc);
        float p = f2.x + f2.y;
        p += __shfl_xor_sync(0xffffffffu, p, 1);
        p += __shfl_xor_sync(0xffffffffu, p, 2);
        pp[i] = p;
    }

    const int i3 = l & 3;
    float v = pp[0];
    if (i3 == 1) v = pp[1];
    if (i3 == 2) v = pp[2];
    if (i3 == 3) v = pp[3];
    const int h = 2 * i3 + (l >> 2);

    const float ex = __expf(v * 0.17677669529663687f * w);   // 1/sqrt(32)
    out_att[(size_t)e * HH + h] = ex;
    atomicAdd(&g_sum[src * HH + h], ex);
}

// ---------------------------------------------------------------------------
// Pass 2: normalize.
// ---------------------------------------------------------------------------
__global__ void __launch_bounds__(256) edge_pass2(
    const int* __restrict__ edge,
    float* __restrict__ out_att)
{
    const int e = blockIdx.x * 256 + threadIdx.x;
    if (e >= EE) return;
    const int src = edge[e];

    const float4* sp = (const float4*)(g_sum + src * HH);
    float4 s0 = sp[0], s1 = sp[1];

    float4* ap = (float4*)(out_att + (size_t)e * HH);
    float4 a0 = ap[0], a1 = ap[1];

    a0.x = __fdividef(a0.x, s0.x + 1e-16f);
    a0.y = __fdividef(a0.y, s0.y + 1e-16f);
    a0.z = __fdividef(a0.z, s0.z + 1e-16f);
    a0.w = __fdividef(a0.w, s0.w + 1e-16f);
    a1.x = __fdividef(a1.x, s1.x + 1e-16f);
    a1.y = __fdividef(a1.y, s1.y + 1e-16f);
    a1.z = __fdividef(a1.z, s1.z + 1e-16f);
    a1.w = __fdividef(a1.w, s1.w + 1e-16f);

    ap[0] = a0; ap[1] = a1;
}

// ---------------------------------------------------------------------------
extern "C" void kernel_launch(void* const* d_in, const int* in_sizes, int n_in,
                              void* d_out, int out_size)
{
    const float* x    = (const float*)d_in[0];
    const int*   edge = (const int*)d_in[1];
    const float* ew   = (const float*)d_in[2];
    const float* Wq   = (const float*)d_in[3];
    const float* bq   = (const float*)d_in[4];
    const float* Wk   = (const float*)d_in[5];
    const float* bk   = (const float*)d_in[6];
    const float* Wv   = (const float*)d_in[7];
    const float* bv   = (const float*)d_in[8];

    float* out_att = (float*)d_out;
    float* out_v   = out_att + (size_t)EE * HH;

    static cudaStream_t s2 = nullptr;
    static cudaEvent_t evFork = nullptr, evJoin = nullptr;
    if (s2 == nullptr) {
        cudaStreamCreateWithFlags(&s2, cudaStreamNonBlocking);
        cudaEventCreateWithFlags(&evFork, cudaEventDisableTiming);
        cudaEventCreateWithFlags(&evJoin, cudaEventDisableTiming);
        cudaFuncSetAttribute(gemm_fused, cudaFuncAttributeMaxDynamicSharedMemorySize, SMEM_V);
    }

    prep_kernel<<<(WGROUPS + ZGROUPS + 255) / 256, 256>>>(Wq, Wk, Wv);

    const int MBLK = (NN + 63) / 64;   // 782

    // qk GEMM (nt 0-3) at full machine width
    gemm_fused<<<MBLK, 256, SMEM_QK>>>(0, 4, x, bq, bk, bv, out_v);

    // fork: v GEMM (nt 4-5) overlaps edge_pass1
    cudaEventRecord(evFork, 0);
    cudaStreamWaitEvent(s2, evFork, 0);
    gemm_fused<<<MBLK, 256, SMEM_V, s2>>>(4, 2, x, bq, bk, bv, out_v);

    edge_pass1<<<EE / 32, 256>>>(edge, ew, out_att);

    edge_pass2<<<(EE + 255) / 256, 256>>>(edge, out_att);

    // join
    cudaEventRecord(evJoin, s2);
    cudaStreamWaitEvent(0, evJoin, 0);
}

// round 13
// speedup vs baseline: 1.3666x; 1.3666x over previous
#include <cuda_runtime.h>
#include <cuda_fp16.h>
#include <cstdint>

#define NN 50000
#define EE 800000
#define KF 256
#define HH 8
#define WROWS 768   // [Wq;Wk;Wv]

// ---------------------------------------------------------------------------
// Scratch (static device globals; no allocation anywhere)
// ---------------------------------------------------------------------------
__device__ __align__(16) __half g_q[(size_t)NN * 256];
__device__ __align__(16) __half g_k[(size_t)NN * 256];
__device__ __align__(16) float g_sum[NN * HH];
__device__ __align__(16) __half g_xh[(size_t)NN * KF];
__device__ __align__(16) __half g_wh[(size_t)WROWS * KF];

// ---------------------------------------------------------------------------
__device__ __forceinline__ uint32_t smem_u32(const void* p) {
    uint32_t a;
    asm("{ .reg .u64 t; cvta.to.shared.u64 t, %1; cvt.u32.u64 %0, t; }" : "=r"(a) : "l"(p));
    return a;
}
__device__ __forceinline__ void ldsm_x4(uint32_t* r, uint32_t addr) {
    asm volatile("ldmatrix.sync.aligned.m8n8.x4.shared.b16 {%0,%1,%2,%3}, [%4];"
                 : "=r"(r[0]), "=r"(r[1]), "=r"(r[2]), "=r"(r[3]) : "r"(addr));
}
__device__ __forceinline__ void mma_f16(float* c, const uint32_t* a, uint32_t b0, uint32_t b1) {
    asm volatile(
        "mma.sync.aligned.m16n8k16.row.col.f32.f16.f16.f32 "
        "{%0,%1,%2,%3}, {%4,%5,%6,%7}, {%8,%9}, {%0,%1,%2,%3};"
        : "+f"(c[0]), "+f"(c[1]), "+f"(c[2]), "+f"(c[3])
        : "r"(a[0]), "r"(a[1]), "r"(a[2]), "r"(a[3]), "r"(b0), "r"(b1));
}
__device__ __forceinline__ void cp_async16(uint32_t smem_addr, const void* gptr, uint32_t src_bytes) {
    asm volatile("cp.async.cg.shared.global [%0], [%1], 16, %2;"
                 :: "r"(smem_addr), "l"(gptr), "r"(src_bytes) : "memory");
}
#define CP_COMMIT() asm volatile("cp.async.commit_group;" ::: "memory")
#define CP_WAIT(n)  asm volatile("cp.async.wait_group %0;" :: "n"(n) : "memory")

// ---------------------------------------------------------------------------
// Convert pre-pass: x -> g_xh (fp16); W concat -> g_wh (fp16); zero g_sum.
// ---------------------------------------------------------------------------
#define XGROUPS (NN * KF / 4)          // 3,200,000
#define WGROUPS (WROWS * KF / 4)       // 49,152
#define ZGROUPS (NN * HH / 4)          // 100,000
__global__ void __launch_bounds__(256) convert_fp16(
    const float* __restrict__ x,
    const float* __restrict__ Wq, const float* __restrict__ Wk, const float* __restrict__ Wv)
{
    int idx = blockIdx.x * 256 + threadIdx.x;
    if (idx >= XGROUPS + WGROUPS) {
        int z = idx - (XGROUPS + WGROUPS);
        if (z < ZGROUPS)
            *(float4*)(g_sum + (size_t)z * 4) = make_float4(0.f, 0.f, 0.f, 0.f);
        return;
    }

    const float* src;
    __half* dst;
    size_t off;
    if (idx < XGROUPS) {
        src = x; off = (size_t)idx * 4;
        dst = g_xh;
    } else {
        int widx = idx - XGROUPS;
        off = (size_t)widx * 4;
        size_t row = off / KF;
        const float* Wm = (row < 256) ? Wq : (row < 512) ? Wk : Wv;
        src = Wm - ((row < 256) ? 0 : (row < 512) ? 256 * KF : 512 * KF);
        dst = g_wh;
    }
    float4 v = *(const float4*)(src + off);
    __half2 p0 = __floats2half2_rn(v.x, v.y);
    __half2 p1 = __floats2half2_rn(v.z, v.w);
    uint2 u;
    u.x = *(uint32_t*)&p0; u.y = *(uint32_t*)&p1;
    *(uint2*)(dst + off) = u;
}

// ---------------------------------------------------------------------------
// Pipelined mma.sync QKV GEMM (fp16): C[N,768] = x @ W^T + b
// nt = ntBase + blockIdx.x : 0-1 -> g_q | 2-3 -> g_k | 4-5 -> out_v (staged)
// BM=128, BN=128, BK=32; 8 warps; 5-stage cp.async circular pipeline
// (prefetch distance 4), ONE __syncthreads per slice. SMEM = 5*20480 = 102400.
// ---------------------------------------------------------------------------
#define NSTAGE 5
#define STAGE_BYTES 20480u   // A(128*40*2=10240) + B(10240)
#define B_OFF 10240u
#define SMEM_GEMM (NSTAGE * STAGE_BYTES)

extern __shared__ char dynsmem[];

__global__ void __launch_bounds__(256, 2) gemm_mma(
    int ntBase,
    const float* __restrict__ bq, const float* __restrict__ bk, const float* __restrict__ bv,
    float* __restrict__ out_v)
{
    const int t = threadIdx.x;
    const int wid = t >> 5;
    const int lane = t & 31;
    const int nt = ntBase + blockIdx.x;
    const int mT = blockIdx.y;      // 0..390
    const bool isV = (nt >= 4);

    const int wm = (wid >> 1) * 32;
    const int wn = (wid & 1) * 64;

    const uint32_t sb = smem_u32(dynsmem);

    const int rA = (lane & 15);
    const int cA = (lane >> 4) << 3;
    const int rB = (lane & 7) + ((lane >> 4) << 3);
    const int cB = ((lane >> 3) & 1) << 3;

    uint32_t addrA[2], addrB[4];
#pragma unroll
    for (int mi = 0; mi < 2; mi++)
        addrA[mi] = sb + (uint32_t)(wm + mi * 16 + rA) * 80u + (uint32_t)cA * 2u;
#pragma unroll
    for (int nf4 = 0; nf4 < 4; nf4++)
        addrB[nf4] = sb + B_OFF + (uint32_t)(wn + nf4 * 16 + rB) * 80u + (uint32_t)cB * 2u;

    float acc[2][8][4];
#pragma unroll
    for (int mi = 0; mi < 2; mi++)
#pragma unroll
        for (int nf = 0; nf < 8; nf++)
#pragma unroll
            for (int i = 0; i < 4; i++) acc[mi][nf][i] = 0.f;

    const int lrow = t >> 1;
    const int lcg = (t & 1) * 16;
    const int growL = mT * 128 + lrow;
    const uint32_t aBytes = (growL < NN) ? 16u : 0u;
    const int brow = nt * 128 + lrow;

    const uint32_t dstA0 = sb + (uint32_t)lrow * 80u + (uint32_t)lcg * 2u;
    const uint32_t dstB0 = sb + B_OFF + (uint32_t)lrow * 80u + (uint32_t)lcg * 2u;

    auto issue = [&](int s) {
        if (s < 8) {
            const uint32_t st = (uint32_t)(s % NSTAGE) * STAGE_BYTES;
            const __half* ap = g_xh + (size_t)growL * KF + s * 32 + lcg;
            const __half* bp = g_wh + (size_t)brow * KF + s * 32 + lcg;
            cp_async16(dstA0 + st, ap, aBytes);
            cp_async16(dstA0 + st + 16, ap + 8, aBytes);
            cp_async16(dstB0 + st, bp, 16u);
            cp_async16(dstB0 + st + 16, bp + 8, 16u);
        }
        CP_COMMIT();
    };

    issue(0); issue(1); issue(2); issue(3);
#pragma unroll
    for (int s = 0; s < 8; s++) {
        CP_WAIT(3);
        __syncthreads();
        issue(s + 4);

        const uint32_t st = (uint32_t)(s % NSTAGE) * STAGE_BYTES;
#pragma unroll
        for (int kk = 0; kk < 2; kk++) {
            uint32_t afrag[2][4];
            ldsm_x4(afrag[0], addrA[0] + st + kk * 32);
            ldsm_x4(afrag[1], addrA[1] + st + kk * 32);
            uint32_t bfrag[4][4];
#pragma unroll
            for (int nf4 = 0; nf4 < 4; nf4++)
                ldsm_x4(bfrag[nf4], addrB[nf4] + st + kk * 32);
#pragma unroll
            for (int mi = 0; mi < 2; mi++)
#pragma unroll
                for (int nf = 0; nf < 8; nf++)
                    mma_f16(acc[mi][nf], afrag[mi],
                            bfrag[nf >> 1][(nf & 1) * 2],
                            bfrag[nf >> 1][(nf & 1) * 2 + 1]);
        }
    }

    const int g = lane >> 2, tg = lane & 3;

    if (!isV) {
        // ---- q/k epilogue: hoisted biases, direct half2 stores ----
        const bool isQ = (nt < 2);
        const float* bptr = isQ ? bq : bk;
        __half* dst = isQ ? g_q : g_k;
        const int colBase = (nt & 1) * 128;
        float bb[8][2];
#pragma unroll
        for (int nf = 0; nf < 8; nf++) {
            const int lc = colBase + wn + nf * 8 + tg * 2;
            bb[nf][0] = __ldg(bptr + lc);
            bb[nf][1] = __ldg(bptr + lc + 1);
        }
#pragma unroll
        for (int mi = 0; mi < 2; mi++) {
            const int r0 = wm + mi * 16 + g;
#pragma unroll
            for (int hh = 0; hh < 2; hh++) {
                const int gr = mT * 128 + r0 + hh * 8;
                if (gr >= NN) continue;
#pragma unroll
                for (int nf = 0; nf < 8; nf++) {
                    const int lc = colBase + wn + nf * 8 + tg * 2;
                    float v0 = acc[mi][nf][hh * 2]     + bb[nf][0];
                    float v1 = acc[mi][nf][hh * 2 + 1] + bb[nf][1];
                    __half2 p2 = __floats2half2_rn(v0, v1);
                    *(__half2*)(dst + (size_t)gr * 256 + lc) = p2;
                }
            }
        }
    } else {
        // ---- v epilogue: stage 64-row halves in SMEM, coalesced float4 out ----
        float* stg = (float*)dynsmem;
        const int wcBase = (nt - 4) * 128;
        float bb[8][2];
#pragma unroll
        for (int nf = 0; nf < 8; nf++) {
            const int c0 = wn + nf * 8 + tg * 2;
            bb[nf][0] = __ldg(bv + wcBase + c0);
            bb[nf][1] = __ldg(bv + wcBase + c0 + 1);
        }
#pragma unroll
        for (int hf = 0; hf < 2; hf++) {
            __syncthreads();
            if ((wm >> 6) == hf) {
#pragma unroll
                for (int mi = 0; mi < 2; mi++) {
#pragma unroll
                    for (int hh = 0; hh < 2; hh++) {
                        const int lr = (wm & 63) + mi * 16 + g + hh * 8;
#pragma unroll
                        for (int nf = 0; nf < 8; nf++) {
                            const int c0 = wn + nf * 8 + tg * 2;
                            float v0 = acc[mi][nf][hh * 2]     + bb[nf][0];
                            float v1 = acc[mi][nf][hh * 2 + 1] + bb[nf][1];
                            stg[lr * 132 + 4 * (c0 & 31) + (c0 >> 5)] = v0;
                            stg[lr * 132 + 4 * ((c0 + 1) & 31) + ((c0 + 1) >> 5)] = v1;
                        }
                    }
                }
            }
            __syncthreads();
#pragma unroll
            for (int it = 0; it < 8; it++) {
                const int idx = it * 256 + t;
                const int r = idx >> 5, d = idx & 31;
                const int gr = mT * 128 + hf * 64 + r;
                if (gr < NN) {
                    float4 v4 = *(float4*)&stg[r * 132 + 4 * d];
                    *(float4*)(out_v + (size_t)gr * 256 + d * 8 + (nt - 4) * 4) = v4;
                }
            }
        }
    }
}

// ---------------------------------------------------------------------------
// Pass 1: 4 edges/warp, 8 lanes/edge, contiguous 16B chunks per lane.
// Per-chunk half2 dot, fp32 promote, 2 xor-shuffle reduce; lane l stores
// head 2*(l&3)+(l>>2) directly.
// ---------------------------------------------------------------------------
__global__ void __launch_bounds__(256) edge_pass1(
    const int* __restrict__ edge,
    const float* __restrict__ ew,
    float* __restrict__ out_att)
{
    const int lane = threadIdx.x & 31;
    const int wid = threadIdx.x >> 5;
    const int e = blockIdx.x * 32 + wid * 4 + (lane >> 3);
    const int l = lane & 7;

    const int src = __ldg(edge + e);
    const int dst = __ldg(edge + EE + e);
    const float w = __ldg(ew + e);

    const uint4* qb = (const uint4*)(g_q + (size_t)src * 256);
    const uint4* kb = (const uint4*)(g_k + (size_t)dst * 256);

    uint4 qv[4], kv[4];
#pragma unroll
    for (int i = 0; i < 4; i++) { qv[i] = qb[i * 8 + l]; kv[i] = kb[i * 8 + l]; }

    float pp[4];
#pragma unroll
    for (int i = 0; i < 4; i++) {
        const __half2* qh = (const __half2*)&qv[i];
        const __half2* kh = (const __half2*)&kv[i];
        __half2 hacc = __hmul2(qh[0], kh[0]);
        hacc = __hfma2(qh[1], kh[1], hacc);
        hacc = __hfma2(qh[2], kh[2], hacc);
        hacc = __hfma2(qh[3], kh[3], hacc);
        float2 f2 = __half22float2(hacc);
        float p = f2.x + f2.y;
        p += __shfl_xor_sync(0xffffffffu, p, 1);
        p += __shfl_xor_sync(0xffffffffu, p, 2);
        pp[i] = p;
    }

    const int i3 = l & 3;
    float v = pp[0];
    if (i3 == 1) v = pp[1];
    if (i3 == 2) v = pp[2];
    if (i3 == 3) v = pp[3];
    const int h = 2 * i3 + (l >> 2);

    const float ex = __expf(v * 0.17677669529663687f * w);   // 1/sqrt(32)
    out_att[(size_t)e * HH + h] = ex;
    atomicAdd(&g_sum[src * HH + h], ex);
}

// ---------------------------------------------------------------------------
// Pass 2: normalize.
// ---------------------------------------------------------------------------
__global__ void __launch_bounds__(256) edge_pass2(
    const int* __restrict__ edge,
    float* __restrict__ out_att)
{
    const int e = blockIdx.x * 256 + threadIdx.x;
    if (e >= EE) return;
    const int src = edge[e];

    const float4* sp = (const float4*)(g_sum + src * HH);
    float4 s0 = sp[0], s1 = sp[1];

    float4* ap = (float4*)(out_att + (size_t)e * HH);
    float4 a0 = ap[0], a1 = ap[1];

    a0.x = __fdividef(a0.x, s0.x + 1e-16f);
    a0.y = __fdividef(a0.y, s0.y + 1e-16f);
    a0.z = __fdividef(a0.z, s0.z + 1e-16f);
    a0.w = __fdividef(a0.w, s0.w + 1e-16f);
    a1.x = __fdividef(a1.x, s1.x + 1e-16f);
    a1.y = __fdividef(a1.y, s1.y + 1e-16f);
    a1.z = __fdividef(a1.z, s1.z + 1e-16f);
    a1.w = __fdividef(a1.w, s1.w + 1e-16f);

    ap[0] = a0; ap[1] = a1;
}

// ---------------------------------------------------------------------------
extern "C" void kernel_launch(void* const* d_in, const int* in_sizes, int n_in,
                              void* d_out, int out_size)
{
    const float* x    = (const float*)d_in[0];
    const int*   edge = (const int*)d_in[1];
    const float* ew   = (const float*)d_in[2];
    const float* Wq   = (const float*)d_in[3];
    const float* bq   = (const float*)d_in[4];
    const float* Wk   = (const float*)d_in[5];
    const float* bk   = (const float*)d_in[6];
    const float* Wv   = (const float*)d_in[7];
    const float* bv   = (const float*)d_in[8];

    float* out_att = (float*)d_out;
    float* out_v   = out_att + (size_t)EE * HH;

    static cudaStream_t s2 = nullptr;
    static cudaEvent_t evFork = nullptr, evJoin = nullptr;
    if (s2 == nullptr) {
        cudaStreamCreateWithFlags(&s2, cudaStreamNonBlocking);
        cudaEventCreateWithFlags(&evFork, cudaEventDisableTiming);
        cudaEventCreateWithFlags(&evJoin, cudaEventDisableTiming);
        cudaFuncSetAttribute(gemm_mma, cudaFuncAttributeMaxDynamicSharedMemorySize, SMEM_GEMM);
    }

    convert_fp16<<<(XGROUPS + WGROUPS + ZGROUPS + 255) / 256, 256>>>(x, Wq, Wk, Wv);

    // fork: v-GEMM runs concurrently with qk-GEMM + edge passes (R9 schedule)
    cudaEventRecord(evFork, 0);
    cudaStreamWaitEvent(s2, evFork, 0);

    dim3 gv(2, (NN + 127) / 128);
    gemm_mma<<<gv, 256, SMEM_GEMM, s2>>>(4, bq, bk, bv, out_v);

    dim3 gqk(4, (NN + 127) / 128);
    gemm_mma<<<gqk, 256, SMEM_GEMM>>>(0, bq, bk, bv, out_v);

    edge_pass1<<<EE / 32, 256>>>(edge, ew, out_att);

    edge_pass2<<<(EE + 255) / 256, 256>>>(edge, out_att);

    // join
    cudaEventRecord(evJoin, s2);
    cudaStreamWaitEvent(0, evJoin, 0);
}